// round 5
// baseline (speedup 1.0000x reference)
#include <cuda_runtime.h>
#include <math.h>

#define KHALF 5
#define KW 11
#define MAXB 16
#define MAXT 2048
#define MAXD 512
#define MAXL 160
#define THRESH 0.9f
#define TS 256              // t-chunk per galpha block
#define ROWS_NEED (TS + 2 * KHALF)   // 266
#define ROWS_PAD  288                // 9 passes * 32 rows

// ---- device scratch ----
__device__ float d_weff[KW * MAXD + 4];     // folded weights; bias at [KW*MAXD]
__device__ float d_apart[MAXB * 8];         // per-(b,chunk) alpha partial sums
__device__ int   d_tfire[MAXB * MAXL];
__device__ int   d_nfinal[MAXB];

// ---------------------------------------------------------------------------
// Fused: blocks [0,NW) fold conv*proj weights; blocks [NW,..) zero the output.
__global__ void k_init(const float* __restrict__ cw, const float* __restrict__ cb,
                       const float* __restrict__ pw, const float* __restrict__ pb,
                       int D, int C, int NW, float* out, int n) {
    if ((int)blockIdx.x < NW) {
        int wid  = blockIdx.x * 8 + (threadIdx.x >> 5);
        int lane = threadIdx.x & 31;
        int NE = KW * D;
        if (wid > NE) return;
        float s = 0.f;
        if (wid == NE) {
            for (int c = lane; c < C; c += 32) s += cb[c] * pw[c];
        } else {
            const float* row = cw + (size_t)wid * C;
            for (int c = lane; c < C; c += 32) s += row[c] * pw[c];
        }
#pragma unroll
        for (int o = 16; o > 0; o >>= 1) s += __shfl_xor_sync(0xffffffffu, s, o);
        if (lane == 0) {
            if (wid == NE) d_weff[KW * MAXD] = s + pb[0];
            else           d_weff[wid] = s;
        }
    } else {
        int bm = blockIdx.x - NW;
        int i = bm * blockDim.x + threadIdx.x;
        int stride = (gridDim.x - NW) * blockDim.x;
        int n4 = n >> 2;
        float4 z = make_float4(0.f, 0.f, 0.f, 0.f);
        float4* p4 = (float4*)out;
        for (int j = i; j < n4; j += stride) p4[j] = z;
        for (int j = n4 * 4 + i; j < n; j += stride) out[j] = 0.f;
    }
}

// ---------------------------------------------------------------------------
// Fused conv-dot + band-sum + sigmoid. Block (c,b) covers t in [c*TS, c*TS+TS).
// Computes g rows locally (with +-5 halo) into smem, then alpha directly.
__global__ void __launch_bounds__(256) k_galpha(const float* __restrict__ e,
                                                float* __restrict__ alpha_out, int T) {
    __shared__ float4 swz[KW * 128];            // 22.5 KB weights
    __shared__ float  sg[ROWS_PAD * 12];        // 13.5 KB g rows (stride 12)
    __shared__ float  red[256];

    int b  = blockIdx.y;
    int t0 = blockIdx.x * TS;
    int tid = threadIdx.x;
    int wid = tid >> 5, lane = tid & 31;

    {
        const float4* w4g = (const float4*)d_weff;
        for (int i = tid; i < KW * 128; i += 256) swz[i] = w4g[i];
    }
    __syncthreads();

    const float4* e4 = (const float4*)e;
#pragma unroll 1
    for (int pass = 0; pass < 9; pass++) {
        int rr0 = pass * 32 + wid * 4;          // local row base (uniform per warp)
        float acc[KW][4];
#pragma unroll
        for (int k = 0; k < KW; k++)
#pragma unroll
            for (int r = 0; r < 4; r++) acc[k][r] = 0.f;

#pragma unroll
        for (int r = 0; r < 4; r++) {
            int rr = rr0 + r;
            int gt = t0 - KHALF + rr;           // global t of this row
            if (rr < ROWS_NEED && gt >= 0 && gt < T) {
                size_t base = ((size_t)b * T + gt) * 128;
                float4 ev[4];
#pragma unroll
                for (int jj = 0; jj < 4; jj++) ev[jj] = e4[base + jj * 32 + lane];
#pragma unroll
                for (int k = 0; k < KW; k++) {
#pragma unroll
                    for (int jj = 0; jj < 4; jj++) {
                        float4 w4 = swz[k * 128 + jj * 32 + lane];
                        acc[k][r] += ev[jj].x * w4.x;
                        acc[k][r] += ev[jj].y * w4.y;
                        acc[k][r] += ev[jj].z * w4.z;
                        acc[k][r] += ev[jj].w * w4.w;
                    }
                }
            }
        }
#pragma unroll
        for (int k = 0; k < KW; k++)
#pragma unroll
            for (int r = 0; r < 4; r++) {
                float v = acc[k][r];
#pragma unroll
                for (int o = 16; o > 0; o >>= 1) v += __shfl_xor_sync(0xffffffffu, v, o);
                acc[k][r] = v;
            }
        if (lane == 0) {
#pragma unroll
            for (int r = 0; r < 4; r++) {
                float* gr = sg + (size_t)(rr0 + r) * 12;
                float4* g4 = (float4*)gr;
                g4[0] = make_float4(acc[0][r], acc[1][r], acc[2][r],  acc[3][r]);
                g4[1] = make_float4(acc[4][r], acc[5][r], acc[6][r],  acc[7][r]);
                g4[2] = make_float4(acc[8][r], acc[9][r], acc[10][r], 0.f);
            }
        }
    }
    __syncthreads();

    // alpha for t = t0 + tid (256 per block)
    float x = d_weff[KW * MAXD];
#pragma unroll
    for (int k = 0; k < KW; k++) x += sg[(tid + k) * 12 + k];
    float a = 1.0f / (1.0f + expf(-x));
    alpha_out[(size_t)b * T + t0 + tid] = a;

    red[tid] = a;
    __syncthreads();
    for (int s = 128; s > 0; s >>= 1) {
        if (tid < s) red[tid] += red[tid + s];
        __syncthreads();
    }
    if (tid == 0) d_apart[b * 8 + blockIdx.x] = red[0];
}

// ---------------------------------------------------------------------------
// Integrate-and-fire: speculative-FADD serial trace (bit-identical to the
// plain sequential loop), then parallel reconstruction via ballot + popcount.
__global__ void k_scan(const float* __restrict__ alpha_out, float* __restrict__ aws,
                       const int* __restrict__ elens, const int* __restrict__ ylens,
                       int T, int Lp1, int nch) {
    __shared__ float sa[MAXT + 16];
    __shared__ float ss[MAXT + 16];
    __shared__ unsigned sword[MAXT / 32];
    __shared__ int scnt[MAXT / 32];
    __shared__ float s_sum;

    int b = blockIdx.x;
    int tid = threadIdx.x;
    int el = elens[b], yl = ylens[b];

    if (tid == 0) {
        float sum = 0.f;
        for (int c = 0; c < nch; c++) sum += d_apart[b * 8 + c];
        s_sum = sum;
    }
    __syncthreads();
    float sum = s_sum;
    float yf = (float)yl;
    for (int t = tid; t < T; t += 256)
        sa[t] = (alpha_out[(size_t)b * T + t] / sum) * yf;
    for (int t = T + tid; t < T + 16; t += 256) sa[t] = 0.f;
    __syncthreads();

    // ---- serial s-trace: speculate 16 FADD steps, roll back on fire
    if (tid == 0) {
        float acc = 0.f;
        int t = 0;
        while (t < el) {
            float s0  = acc + sa[t + 0];
            float s1  = s0  + sa[t + 1];
            float s2  = s1  + sa[t + 2];
            float s3  = s2  + sa[t + 3];
            float s4  = s3  + sa[t + 4];
            float s5  = s4  + sa[t + 5];
            float s6  = s5  + sa[t + 6];
            float s7  = s6  + sa[t + 7];
            float s8  = s7  + sa[t + 8];
            float s9  = s8  + sa[t + 9];
            float s10 = s9  + sa[t + 10];
            float s11 = s10 + sa[t + 11];
            float s12 = s11 + sa[t + 12];
            float s13 = s12 + sa[t + 13];
            float s14 = s13 + sa[t + 14];
            float s15 = s14 + sa[t + 15];
            ss[t + 0]  = s0;  ss[t + 1]  = s1;  ss[t + 2]  = s2;  ss[t + 3]  = s3;
            ss[t + 4]  = s4;  ss[t + 5]  = s5;  ss[t + 6]  = s6;  ss[t + 7]  = s7;
            ss[t + 8]  = s8;  ss[t + 9]  = s9;  ss[t + 10] = s10; ss[t + 11] = s11;
            ss[t + 12] = s12; ss[t + 13] = s13; ss[t + 14] = s14; ss[t + 15] = s15;
            unsigned m = 0;
            m |= (s0  >= THRESH) ? 1u       : 0u;
            m |= (s1  >= THRESH) ? 2u       : 0u;
            m |= (s2  >= THRESH) ? 4u       : 0u;
            m |= (s3  >= THRESH) ? 8u       : 0u;
            m |= (s4  >= THRESH) ? 16u      : 0u;
            m |= (s5  >= THRESH) ? 32u      : 0u;
            m |= (s6  >= THRESH) ? 64u      : 0u;
            m |= (s7  >= THRESH) ? 128u     : 0u;
            m |= (s8  >= THRESH) ? 256u     : 0u;
            m |= (s9  >= THRESH) ? 512u     : 0u;
            m |= (s10 >= THRESH) ? 1024u    : 0u;
            m |= (s11 >= THRESH) ? 2048u    : 0u;
            m |= (s12 >= THRESH) ? 4096u    : 0u;
            m |= (s13 >= THRESH) ? 8192u    : 0u;
            m |= (s14 >= THRESH) ? 16384u   : 0u;
            m |= (s15 >= THRESH) ? 32768u   : 0u;
            if (m == 0) {
                acc = s15;
                t += 16;
            } else {
                int j = __ffs(m) - 1;
                acc = ss[t + j] + (sa[t + j] - 1.0f);
                t += j + 1;
            }
        }
    }
    __syncthreads();

    // ---- candidate ballots
    for (int t = tid; t < T; t += 256) {
        bool cand = (t < el) && (ss[t] >= THRESH);
        unsigned bal = __ballot_sync(0xffffffffu, cand);
        if ((t & 31) == 0) { sword[t >> 5] = bal; scnt[t >> 5] = __popc(bal); }
    }
    __syncthreads();
    if (tid == 0) {
        int run = 0, nw = T >> 5;
        for (int w = 0; w < nw; w++) { int c = scnt[w]; scnt[w] = run; run += c; }
        d_nfinal[b] = run < yl ? run : yl;
    }
    __syncthreads();
    // ---- reconstruct weights, write aws + fire times
    float* awb = aws + (size_t)b * Lp1 * T;
    for (int t = tid; t < T; t += 256) {
        if (t >= el) continue;
        float s = ss[t];
        float a = sa[t];
        unsigned w = sword[t >> 5];
        int rank = scnt[t >> 5] + __popc(w & ((1u << (t & 31)) - 1u));
        if (rank >= yl) continue;
        bool fire = (s >= THRESH);
        float wold = fire ? (1.0f - s) : a;
        awb[(size_t)rank * T + t] = wold;
        if (fire) {
            awb[(size_t)(rank + 1) * T + t] = s + (a - 1.0f);
            d_tfire[b * MAXL + rank] = t;
        }
    }
}

// ---------------------------------------------------------------------------
// fired[b,l,:] = sum_{t in segment} aws[b,l,t] * eouts[b,t,:]
__global__ void k_fired(const float* __restrict__ e, const float* __restrict__ aws,
                        float* __restrict__ fired, int T, int D, int L) {
    int b = blockIdx.y, l = blockIdx.x;
    if (l >= d_nfinal[b]) return;
    int tlo = (l == 0) ? 0 : d_tfire[b * MAXL + l - 1];
    int thi = d_tfire[b * MAXL + l];
    const float* awr = aws + ((size_t)b * (L + 1) + l) * T;
    const float4* eb = (const float4*)(e + (size_t)b * T * D);
    int d4 = threadIdx.x;
    float4 acc = make_float4(0.f, 0.f, 0.f, 0.f);
#pragma unroll 4
    for (int t = tlo; t <= thi; t++) {
        float w = awr[t];
        float4 ev = eb[(size_t)t * (D / 4) + d4];
        acc.x += w * ev.x; acc.y += w * ev.y;
        acc.z += w * ev.z; acc.w += w * ev.w;
    }
    ((float4*)(fired + ((size_t)b * L + l) * D))[d4] = acc;
}

// ---------------------------------------------------------------------------
extern "C" void kernel_launch(void* const* d_in, const int* in_sizes, int n_in,
                              void* d_out, int out_size) {
    const float* eouts  = (const float*)d_in[0];
    const float* conv_w = (const float*)d_in[1];
    const float* conv_b = (const float*)d_in[2];
    const float* proj_w = (const float*)d_in[3];
    const float* proj_b = (const float*)d_in[4];
    const int*   elens  = (const int*)d_in[5];
    const int*   ylens  = (const int*)d_in[6];

    int B = in_sizes[5];
    int C = in_sizes[2];
    int D = in_sizes[1] / (KW * C);
    int T = in_sizes[0] / (B * D);
    int L = (out_size - 2 * B * T) / (B * (D + T));

    float* fired   = (float*)d_out;
    float* alpha_o = fired + (size_t)B * L * D;
    float* aws     = alpha_o + (size_t)B * T;

    int NW = (KW * D + 1 + 7) / 8;          // weff blocks (8 warps each)

    k_init<<<NW + 512, 256>>>(conv_w, conv_b, proj_w, proj_b, D, C, NW,
                              (float*)d_out, out_size);
    k_galpha<<<dim3(T / TS, B), 256>>>(eouts, alpha_o, T);
    k_scan<<<B, 256>>>(alpha_o, aws, elens, ylens, T, L + 1, T / TS);
    k_fired<<<dim3(L, B), 128>>>(eouts, aws, fired, T, D, L);
}